// round 1
// baseline (speedup 1.0000x reference)
#include <cuda_runtime.h>
#include <math.h>

#define BB 4
#define NN 8192
#define SS 512
#define EE 512
#define CCH 1536
#define MCH 512
#define RR (BB*NN)   // 32768 rows

// ---------------- scratch (static device globals; no allocation) ----------------
static __device__ float g_interp[(size_t)RR * CCH];  // 201 MB
static __device__ float g_x1[(size_t)RR * MCH];      // 67 MB (pre-BN layer1)
static __device__ float g_x2[(size_t)RR * MCH];      // 67 MB (pre-BN layer2)
static __device__ int   g_kidx[RR * 3];
static __device__ float g_kw[RR * 3];
static __device__ float g_stats[4 * MCH];            // sum1, sq1, sum2, sq2
static __device__ float g_affine[4 * MCH];           // scale1, shift1, scale2, shift2

// ---------------- zero stats ----------------
__global__ void zero_stats_kernel() {
    int i = blockIdx.x * blockDim.x + threadIdx.x;
    if (i < 4 * MCH) g_stats[i] = 0.0f;
}

// ---------------- KNN (top-3 smallest squared distances) ----------------
__global__ void knn_kernel(const float* __restrict__ xyz,
                           const float* __restrict__ centers) {
    __shared__ float sc[SS * 3];
    __shared__ float scn[SS];
    int p = blockIdx.x * blockDim.x + threadIdx.x;   // global point, blocks don't straddle batches
    int b = p >> 13;                                  // /8192
    for (int i = threadIdx.x; i < SS * 3; i += blockDim.x)
        sc[i] = centers[b * SS * 3 + i];
    __syncthreads();
    for (int s = threadIdx.x; s < SS; s += blockDim.x) {
        float c0 = sc[s*3], c1 = sc[s*3+1], c2 = sc[s*3+2];
        scn[s] = c0*c0 + c1*c1 + c2*c2;
    }
    __syncthreads();

    float x0 = xyz[p*3+0], x1 = xyz[p*3+1], x2 = xyz[p*3+2];
    float xx = x0*x0 + x1*x1 + x2*x2;

    float bd0 = 3.4e38f, bd1 = 3.4e38f, bd2 = 3.4e38f;
    int   bi0 = 0, bi1 = 0, bi2 = 0;
    for (int s = 0; s < SS; s++) {
        float c0 = sc[s*3], c1 = sc[s*3+1], c2 = sc[s*3+2];
        // match reference expansion: ||x||^2 - 2 x.c + ||c||^2
        float dot = x0*c0 + x1*c1 + x2*c2;
        float d = xx - 2.0f * dot + scn[s];
        if (d < bd2) {
            if (d < bd1) {
                bd2 = bd1; bi2 = bi1;
                if (d < bd0) { bd1 = bd0; bi1 = bi0; bd0 = d; bi0 = s; }
                else         { bd1 = d;  bi1 = s; }
            } else { bd2 = d; bi2 = s; }
        }
    }
    float r0 = 1.0f / (bd0 + 1e-8f);
    float r1 = 1.0f / (bd1 + 1e-8f);
    float r2 = 1.0f / (bd2 + 1e-8f);
    float inv = 1.0f / (r0 + r1 + r2);
    g_kidx[p*3+0] = bi0; g_kidx[p*3+1] = bi1; g_kidx[p*3+2] = bi2;
    g_kw[p*3+0] = r0 * inv; g_kw[p*3+1] = r1 * inv; g_kw[p*3+2] = r2 * inv;
}

// ---------------- interpolation: g_interp[p, :] = sum_k w_k * fused[b, idx_k, :] ----------------
// fused channel layout: [0,512)->H4, [512,1024)->H8, [1024,1536)->H12
__global__ void interp_kernel(const float* __restrict__ H4,
                              const float* __restrict__ H8,
                              const float* __restrict__ H12) {
    int p = blockIdx.x;
    int b = p >> 13;
    __shared__ int   si[3];
    __shared__ float sw[3];
    if (threadIdx.x < 3) {
        si[threadIdx.x] = g_kidx[p*3 + threadIdx.x];
        sw[threadIdx.x] = g_kw[p*3 + threadIdx.x];
    }
    __syncthreads();
    int c4  = threadIdx.x;        // 0..383 (float4 index within 1536-ch row)
    int sec = c4 >> 7;            // which source tensor
    int off = c4 & 127;           // float4 within 512-ch row
    const float* src = (sec == 0) ? H4 : ((sec == 1) ? H8 : H12);
    const float4* base = (const float4*)src + (size_t)b * SS * 128;

    float4 a = make_float4(0.f, 0.f, 0.f, 0.f);
#pragma unroll
    for (int k = 0; k < 3; k++) {
        float4 v = base[si[k] * 128 + off];
        float w = sw[k];
        a.x += w * v.x; a.y += w * v.y; a.z += w * v.z; a.w += w * v.w;
    }
    ((float4*)g_interp)[(size_t)p * 384 + c4] = a;
}

// ---------------- 128x128x8 fp32 SGEMM, 8x8 per thread ----------------
// out[row, col] = sum_k A[row,k] * W[col,k] + bias[col]
// LAYER==0: A = g_interp (K=1536), out = g_x1
// LAYER==1: A = relu(g_x1 * scale1 + shift1) (K=512), out = g_x2
template<int K, int LAYER>
__global__ void __launch_bounds__(256, 2)
sgemm_kernel(const float* __restrict__ W, const float* __restrict__ bias) {
    __shared__ float As[8][128];
    __shared__ float Ws[8][128];

    const float* A     = (LAYER == 0) ? g_interp : g_x1;
    float*       out   = (LAYER == 0) ? g_x1     : g_x2;
    const float* scale = g_affine;        // scale1
    const float* shift = g_affine + MCH;  // shift1

    int tid  = threadIdx.x;
    int brow = blockIdx.y * 128;
    int bcol = blockIdx.x * 128;

    int lr = tid >> 1;             // 0..127: row within tile (for loads)
    int lh = (tid & 1) * 4;        // k sub-offset 0 or 4
    const float* Ag = A + (size_t)(brow + lr) * K + lh;
    const float* Wg = W + (size_t)(bcol + lr) * K + lh;

    int trow = (tid >> 4) * 8;     // compute row base in tile
    int tcol = (tid & 15) * 8;     // compute col base in tile

    float acc[8][8];
#pragma unroll
    for (int i = 0; i < 8; i++)
#pragma unroll
        for (int j = 0; j < 8; j++) acc[i][j] = 0.f;

    const int nk = K / 8;

    // prologue load of tile 0
    float4 ra = *(const float4*)(Ag);
    float4 rw = *(const float4*)(Wg);
    if (LAYER == 1) {
        int k0 = lh;
        float4 s  = *(const float4*)(scale + k0);
        float4 sh = *(const float4*)(shift + k0);
        ra.x = fmaxf(fmaf(ra.x, s.x, sh.x), 0.f);
        ra.y = fmaxf(fmaf(ra.y, s.y, sh.y), 0.f);
        ra.z = fmaxf(fmaf(ra.z, s.z, sh.z), 0.f);
        ra.w = fmaxf(fmaf(ra.w, s.w, sh.w), 0.f);
    }

    for (int t = 0; t < nk; t++) {
        // commit current tile to smem (transposed: [k][row])
        As[lh+0][lr] = ra.x; As[lh+1][lr] = ra.y; As[lh+2][lr] = ra.z; As[lh+3][lr] = ra.w;
        Ws[lh+0][lr] = rw.x; Ws[lh+1][lr] = rw.y; Ws[lh+2][lr] = rw.z; Ws[lh+3][lr] = rw.w;
        __syncthreads();

        // prefetch next tile into registers
        if (t + 1 < nk) {
            ra = *(const float4*)(Ag + (size_t)(t+1) * 8);
            rw = *(const float4*)(Wg + (size_t)(t+1) * 8);
            if (LAYER == 1) {
                int k0 = (t+1) * 8 + lh;
                float4 s  = *(const float4*)(scale + k0);
                float4 sh = *(const float4*)(shift + k0);
                ra.x = fmaxf(fmaf(ra.x, s.x, sh.x), 0.f);
                ra.y = fmaxf(fmaf(ra.y, s.y, sh.y), 0.f);
                ra.z = fmaxf(fmaf(ra.z, s.z, sh.z), 0.f);
                ra.w = fmaxf(fmaf(ra.w, s.w, sh.w), 0.f);
            }
        }

#pragma unroll
        for (int k = 0; k < 8; k++) {
            float a[8], w[8];
            *(float4*)(a)     = *(const float4*)&As[k][trow];
            *(float4*)(a + 4) = *(const float4*)&As[k][trow + 4];
            *(float4*)(w)     = *(const float4*)&Ws[k][tcol];
            *(float4*)(w + 4) = *(const float4*)&Ws[k][tcol + 4];
#pragma unroll
            for (int i = 0; i < 8; i++)
#pragma unroll
                for (int j = 0; j < 8; j++)
                    acc[i][j] = fmaf(a[i], w[j], acc[i][j]);
        }
        __syncthreads();
    }

    float4 bl = *(const float4*)(bias + bcol + tcol);
    float4 bh = *(const float4*)(bias + bcol + tcol + 4);
    float bb_[8] = {bl.x, bl.y, bl.z, bl.w, bh.x, bh.y, bh.z, bh.w};

#pragma unroll
    for (int i = 0; i < 8; i++) {
        size_t row = (size_t)(brow + trow + i);
        float4 v0 = make_float4(acc[i][0] + bb_[0], acc[i][1] + bb_[1],
                                acc[i][2] + bb_[2], acc[i][3] + bb_[3]);
        float4 v1 = make_float4(acc[i][4] + bb_[4], acc[i][5] + bb_[5],
                                acc[i][6] + bb_[6], acc[i][7] + bb_[7]);
        *(float4*)&out[row * MCH + bcol + tcol]     = v0;
        *(float4*)&out[row * MCH + bcol + tcol + 4] = v1;
    }
}

// ---------------- per-channel sum / sumsq over 32768 rows ----------------
__global__ void colstats_kernel(int layer) {
    const float* x = layer ? g_x2 : g_x1;
    float* sum = &g_stats[layer * 2 * MCH];
    float* sq  = sum + MCH;
    int c0 = threadIdx.x;                 // 0..255
    int rbase = blockIdx.x * 128;
    float s0 = 0.f, q0 = 0.f, s1 = 0.f, q1 = 0.f;
    for (int r = 0; r < 128; r++) {
        const float* row = x + (size_t)(rbase + r) * MCH;
        float v0 = row[c0];
        float v1 = row[c0 + 256];
        s0 += v0; q0 += v0 * v0;
        s1 += v1; q1 += v1 * v1;
    }
    atomicAdd(&sum[c0], s0);       atomicAdd(&sq[c0], q0);
    atomicAdd(&sum[c0 + 256], s1); atomicAdd(&sq[c0 + 256], q1);
}

// ---------------- BN finalize: scale = g*rstd, shift = beta - mean*scale ----------------
__global__ void finalize_kernel(const float* __restrict__ gamma,
                                const float* __restrict__ beta, int layer) {
    int c = threadIdx.x;   // 512 threads
    float mean = g_stats[layer * 2 * MCH + c] * (1.0f / RR);
    float var  = g_stats[layer * 2 * MCH + MCH + c] * (1.0f / RR) - mean * mean;
    float rstd = rsqrtf(var + 1e-5f);
    float sc = gamma[c] * rstd;
    g_affine[layer * 2 * MCH + c]       = sc;
    g_affine[layer * 2 * MCH + MCH + c] = beta[c] - mean * sc;
}

// ---------------- final map: out = relu(x2 * scale2 + shift2) ----------------
__global__ void finalmap_kernel(float* __restrict__ out) {
    int i = blockIdx.x * blockDim.x + threadIdx.x;   // float4 index: RR*128 total
    int c4 = i & 127;
    float4 v  = ((const float4*)g_x2)[i];
    float4 s  = ((const float4*)(g_affine + 2 * MCH))[c4];
    float4 t  = ((const float4*)(g_affine + 3 * MCH))[c4];
    v.x = fmaxf(fmaf(v.x, s.x, t.x), 0.f);
    v.y = fmaxf(fmaf(v.y, s.y, t.y), 0.f);
    v.z = fmaxf(fmaf(v.z, s.z, t.z), 0.f);
    v.w = fmaxf(fmaf(v.w, s.w, t.w), 0.f);
    ((float4*)out)[i] = v;
}

// ---------------- launch ----------------
extern "C" void kernel_launch(void* const* d_in, const int* in_sizes, int n_in,
                              void* d_out, int out_size) {
    const float* xyz     = (const float*)d_in[0];
    const float* centers = (const float*)d_in[1];
    const float* H4      = (const float*)d_in[2];
    const float* H8      = (const float*)d_in[3];
    const float* H12     = (const float*)d_in[4];
    const float* W1      = (const float*)d_in[5];
    const float* b1      = (const float*)d_in[6];
    const float* g1      = (const float*)d_in[7];
    const float* beta1   = (const float*)d_in[8];
    const float* W2      = (const float*)d_in[9];
    const float* b2      = (const float*)d_in[10];
    const float* g2      = (const float*)d_in[11];
    const float* beta2   = (const float*)d_in[12];
    float* out = (float*)d_out;

    zero_stats_kernel<<<2, 1024>>>();
    knn_kernel<<<RR / 256, 256>>>(xyz, centers);
    interp_kernel<<<RR, 384>>>(H4, H8, H12);

    dim3 g1d(MCH / 128, RR / 128);   // (4, 256)
    sgemm_kernel<CCH, 0><<<g1d, 256>>>(W1, b1);

    colstats_kernel<<<RR / 128, 256>>>(0);
    finalize_kernel<<<1, 512>>>(g1, beta1, 0);

    sgemm_kernel<MCH, 1><<<g1d, 256>>>(W2, b2);

    colstats_kernel<<<RR / 128, 256>>>(1);
    finalize_kernel<<<1, 512>>>(g2, beta2, 1);

    finalmap_kernel<<<(RR * 128) / 256, 256>>>(out);
}

// round 2
// speedup vs baseline: 1.0001x; 1.0001x over previous
#include <cuda_runtime.h>
#include <math.h>

#define BB 4
#define NN 8192
#define SS 512
#define EE 512
#define CCH 1536
#define MCH 512
#define RR (BB*NN)   // 32768 rows

// ---------------- scratch (static device globals; no allocation) ----------------
static __device__ float g_interp[(size_t)RR * CCH];  // 201 MB
static __device__ float g_x1[(size_t)RR * MCH];      // 67 MB (pre-BN layer1)
static __device__ float g_x2[(size_t)RR * MCH];      // 67 MB (pre-BN layer2)
static __device__ int   g_kidx[RR * 3];
static __device__ float g_kw[RR * 3];
static __device__ float g_stats[4 * MCH];            // sum1, sq1, sum2, sq2
static __device__ float g_affine[4 * MCH];           // scale1, shift1, scale2, shift2

// ---------------- zero stats ----------------
__global__ void zero_stats_kernel() {
    int i = blockIdx.x * blockDim.x + threadIdx.x;
    if (i < 4 * MCH) g_stats[i] = 0.0f;
}

// ---------------- KNN (top-3 smallest squared distances) ----------------
__global__ void knn_kernel(const float* __restrict__ xyz,
                           const float* __restrict__ centers) {
    __shared__ float sc[SS * 3];
    __shared__ float scn[SS];
    int p = blockIdx.x * blockDim.x + threadIdx.x;   // global point, blocks don't straddle batches
    int b = p >> 13;                                  // /8192
    for (int i = threadIdx.x; i < SS * 3; i += blockDim.x)
        sc[i] = centers[b * SS * 3 + i];
    __syncthreads();
    for (int s = threadIdx.x; s < SS; s += blockDim.x) {
        float c0 = sc[s*3], c1 = sc[s*3+1], c2 = sc[s*3+2];
        scn[s] = c0*c0 + c1*c1 + c2*c2;
    }
    __syncthreads();

    float x0 = xyz[p*3+0], x1 = xyz[p*3+1], x2 = xyz[p*3+2];
    float xx = x0*x0 + x1*x1 + x2*x2;

    float bd0 = 3.4e38f, bd1 = 3.4e38f, bd2 = 3.4e38f;
    int   bi0 = 0, bi1 = 0, bi2 = 0;
    for (int s = 0; s < SS; s++) {
        float c0 = sc[s*3], c1 = sc[s*3+1], c2 = sc[s*3+2];
        // match reference expansion: ||x||^2 - 2 x.c + ||c||^2
        float dot = x0*c0 + x1*c1 + x2*c2;
        float d = xx - 2.0f * dot + scn[s];
        if (d < bd2) {
            if (d < bd1) {
                bd2 = bd1; bi2 = bi1;
                if (d < bd0) { bd1 = bd0; bi1 = bi0; bd0 = d; bi0 = s; }
                else         { bd1 = d;  bi1 = s; }
            } else { bd2 = d; bi2 = s; }
        }
    }
    float r0 = 1.0f / (bd0 + 1e-8f);
    float r1 = 1.0f / (bd1 + 1e-8f);
    float r2 = 1.0f / (bd2 + 1e-8f);
    float inv = 1.0f / (r0 + r1 + r2);
    g_kidx[p*3+0] = bi0; g_kidx[p*3+1] = bi1; g_kidx[p*3+2] = bi2;
    g_kw[p*3+0] = r0 * inv; g_kw[p*3+1] = r1 * inv; g_kw[p*3+2] = r2 * inv;
}

// ---------------- interpolation: g_interp[p, :] = sum_k w_k * fused[b, idx_k, :] ----------------
// fused channel layout: [0,512)->H4, [512,1024)->H8, [1024,1536)->H12
__global__ void interp_kernel(const float* __restrict__ H4,
                              const float* __restrict__ H8,
                              const float* __restrict__ H12) {
    int p = blockIdx.x;
    int b = p >> 13;
    __shared__ int   si[3];
    __shared__ float sw[3];
    if (threadIdx.x < 3) {
        si[threadIdx.x] = g_kidx[p*3 + threadIdx.x];
        sw[threadIdx.x] = g_kw[p*3 + threadIdx.x];
    }
    __syncthreads();
    int c4  = threadIdx.x;        // 0..383 (float4 index within 1536-ch row)
    int sec = c4 >> 7;            // which source tensor
    int off = c4 & 127;           // float4 within 512-ch row
    const float* src = (sec == 0) ? H4 : ((sec == 1) ? H8 : H12);
    const float4* base = (const float4*)src + (size_t)b * SS * 128;

    float4 a = make_float4(0.f, 0.f, 0.f, 0.f);
#pragma unroll
    for (int k = 0; k < 3; k++) {
        float4 v = base[si[k] * 128 + off];
        float w = sw[k];
        a.x += w * v.x; a.y += w * v.y; a.z += w * v.z; a.w += w * v.w;
    }
    ((float4*)g_interp)[(size_t)p * 384 + c4] = a;
}

// ---------------- 128x128x8 fp32 SGEMM, 8x8 per thread ----------------
// out[row, col] = sum_k A[row,k] * W[col,k] + bias[col]
// LAYER==0: A = g_interp (K=1536), out = g_x1
// LAYER==1: A = relu(g_x1 * scale1 + shift1) (K=512), out = g_x2
template<int K, int LAYER>
__global__ void __launch_bounds__(256, 2)
sgemm_kernel(const float* __restrict__ W, const float* __restrict__ bias) {
    __shared__ float As[8][128];
    __shared__ float Ws[8][128];

    const float* A     = (LAYER == 0) ? g_interp : g_x1;
    float*       out   = (LAYER == 0) ? g_x1     : g_x2;
    const float* scale = g_affine;        // scale1
    const float* shift = g_affine + MCH;  // shift1

    int tid  = threadIdx.x;
    int brow = blockIdx.y * 128;
    int bcol = blockIdx.x * 128;

    int lr = tid >> 1;             // 0..127: row within tile (for loads)
    int lh = (tid & 1) * 4;        // k sub-offset 0 or 4
    const float* Ag = A + (size_t)(brow + lr) * K + lh;
    const float* Wg = W + (size_t)(bcol + lr) * K + lh;

    int trow = (tid >> 4) * 8;     // compute row base in tile
    int tcol = (tid & 15) * 8;     // compute col base in tile

    float acc[8][8];
#pragma unroll
    for (int i = 0; i < 8; i++)
#pragma unroll
        for (int j = 0; j < 8; j++) acc[i][j] = 0.f;

    const int nk = K / 8;

    // prologue load of tile 0
    float4 ra = *(const float4*)(Ag);
    float4 rw = *(const float4*)(Wg);
    if (LAYER == 1) {
        int k0 = lh;
        float4 s  = *(const float4*)(scale + k0);
        float4 sh = *(const float4*)(shift + k0);
        ra.x = fmaxf(fmaf(ra.x, s.x, sh.x), 0.f);
        ra.y = fmaxf(fmaf(ra.y, s.y, sh.y), 0.f);
        ra.z = fmaxf(fmaf(ra.z, s.z, sh.z), 0.f);
        ra.w = fmaxf(fmaf(ra.w, s.w, sh.w), 0.f);
    }

    for (int t = 0; t < nk; t++) {
        // commit current tile to smem (transposed: [k][row])
        As[lh+0][lr] = ra.x; As[lh+1][lr] = ra.y; As[lh+2][lr] = ra.z; As[lh+3][lr] = ra.w;
        Ws[lh+0][lr] = rw.x; Ws[lh+1][lr] = rw.y; Ws[lh+2][lr] = rw.z; Ws[lh+3][lr] = rw.w;
        __syncthreads();

        // prefetch next tile into registers
        if (t + 1 < nk) {
            ra = *(const float4*)(Ag + (size_t)(t+1) * 8);
            rw = *(const float4*)(Wg + (size_t)(t+1) * 8);
            if (LAYER == 1) {
                int k0 = (t+1) * 8 + lh;
                float4 s  = *(const float4*)(scale + k0);
                float4 sh = *(const float4*)(shift + k0);
                ra.x = fmaxf(fmaf(ra.x, s.x, sh.x), 0.f);
                ra.y = fmaxf(fmaf(ra.y, s.y, sh.y), 0.f);
                ra.z = fmaxf(fmaf(ra.z, s.z, sh.z), 0.f);
                ra.w = fmaxf(fmaf(ra.w, s.w, sh.w), 0.f);
            }
        }

#pragma unroll
        for (int k = 0; k < 8; k++) {
            float a[8], w[8];
            *(float4*)(a)     = *(const float4*)&As[k][trow];
            *(float4*)(a + 4) = *(const float4*)&As[k][trow + 4];
            *(float4*)(w)     = *(const float4*)&Ws[k][tcol];
            *(float4*)(w + 4) = *(const float4*)&Ws[k][tcol + 4];
#pragma unroll
            for (int i = 0; i < 8; i++)
#pragma unroll
                for (int j = 0; j < 8; j++)
                    acc[i][j] = fmaf(a[i], w[j], acc[i][j]);
        }
        __syncthreads();
    }

    float4 bl = *(const float4*)(bias + bcol + tcol);
    float4 bh = *(const float4*)(bias + bcol + tcol + 4);
    float bb_[8] = {bl.x, bl.y, bl.z, bl.w, bh.x, bh.y, bh.z, bh.w};

#pragma unroll
    for (int i = 0; i < 8; i++) {
        size_t row = (size_t)(brow + trow + i);
        float4 v0 = make_float4(acc[i][0] + bb_[0], acc[i][1] + bb_[1],
                                acc[i][2] + bb_[2], acc[i][3] + bb_[3]);
        float4 v1 = make_float4(acc[i][4] + bb_[4], acc[i][5] + bb_[5],
                                acc[i][6] + bb_[6], acc[i][7] + bb_[7]);
        *(float4*)&out[row * MCH + bcol + tcol]     = v0;
        *(float4*)&out[row * MCH + bcol + tcol + 4] = v1;
    }
}

// ---------------- per-channel sum / sumsq over 32768 rows ----------------
__global__ void colstats_kernel(int layer) {
    const float* x = layer ? g_x2 : g_x1;
    float* sum = &g_stats[layer * 2 * MCH];
    float* sq  = sum + MCH;
    int c0 = threadIdx.x;                 // 0..255
    int rbase = blockIdx.x * 128;
    float s0 = 0.f, q0 = 0.f, s1 = 0.f, q1 = 0.f;
    for (int r = 0; r < 128; r++) {
        const float* row = x + (size_t)(rbase + r) * MCH;
        float v0 = row[c0];
        float v1 = row[c0 + 256];
        s0 += v0; q0 += v0 * v0;
        s1 += v1; q1 += v1 * v1;
    }
    atomicAdd(&sum[c0], s0);       atomicAdd(&sq[c0], q0);
    atomicAdd(&sum[c0 + 256], s1); atomicAdd(&sq[c0 + 256], q1);
}

// ---------------- BN finalize: scale = g*rstd, shift = beta - mean*scale ----------------
__global__ void finalize_kernel(const float* __restrict__ gamma,
                                const float* __restrict__ beta, int layer) {
    int c = threadIdx.x;   // 512 threads
    float mean = g_stats[layer * 2 * MCH + c] * (1.0f / RR);
    float var  = g_stats[layer * 2 * MCH + MCH + c] * (1.0f / RR) - mean * mean;
    float rstd = rsqrtf(var + 1e-5f);
    float sc = gamma[c] * rstd;
    g_affine[layer * 2 * MCH + c]       = sc;
    g_affine[layer * 2 * MCH + MCH + c] = beta[c] - mean * sc;
}

// ---------------- final map: out = relu(x2 * scale2 + shift2) ----------------
__global__ void finalmap_kernel(float* __restrict__ out) {
    int i = blockIdx.x * blockDim.x + threadIdx.x;   // float4 index: RR*128 total
    int c4 = i & 127;
    float4 v  = ((const float4*)g_x2)[i];
    float4 s  = ((const float4*)(g_affine + 2 * MCH))[c4];
    float4 t  = ((const float4*)(g_affine + 3 * MCH))[c4];
    v.x = fmaxf(fmaf(v.x, s.x, t.x), 0.f);
    v.y = fmaxf(fmaf(v.y, s.y, t.y), 0.f);
    v.z = fmaxf(fmaf(v.z, s.z, t.z), 0.f);
    v.w = fmaxf(fmaf(v.w, s.w, t.w), 0.f);
    ((float4*)out)[i] = v;
}

// ---------------- launch ----------------
extern "C" void kernel_launch(void* const* d_in, const int* in_sizes, int n_in,
                              void* d_out, int out_size) {
    const float* xyz     = (const float*)d_in[0];
    const float* centers = (const float*)d_in[1];
    const float* H4      = (const float*)d_in[2];
    const float* H8      = (const float*)d_in[3];
    const float* H12     = (const float*)d_in[4];
    const float* W1      = (const float*)d_in[5];
    const float* b1      = (const float*)d_in[6];
    const float* g1      = (const float*)d_in[7];
    const float* beta1   = (const float*)d_in[8];
    const float* W2      = (const float*)d_in[9];
    const float* b2      = (const float*)d_in[10];
    const float* g2      = (const float*)d_in[11];
    const float* beta2   = (const float*)d_in[12];
    float* out = (float*)d_out;

    zero_stats_kernel<<<2, 1024>>>();
    knn_kernel<<<RR / 256, 256>>>(xyz, centers);
    interp_kernel<<<RR, 384>>>(H4, H8, H12);

    dim3 g1d(MCH / 128, RR / 128);   // (4, 256)
    sgemm_kernel<CCH, 0><<<g1d, 256>>>(W1, b1);

    colstats_kernel<<<RR / 128, 256>>>(0);
    finalize_kernel<<<1, 512>>>(g1, beta1, 0);

    sgemm_kernel<MCH, 1><<<g1d, 256>>>(W2, b2);

    colstats_kernel<<<RR / 128, 256>>>(1);
    finalize_kernel<<<1, 512>>>(g2, beta2, 1);

    finalmap_kernel<<<(RR * 128) / 256, 256>>>(out);
}

// round 5
// speedup vs baseline: 2.0590x; 2.0587x over previous
#include <cuda_runtime.h>
#include <cuda_bf16.h>
#include <cstdint>
#include <math.h>

#define BB 4
#define NN 8192
#define SS 512
#define CCH 1536
#define MCH 512
#define RR (BB*NN)   // 32768 rows

// ---------------- scratch (static device globals; no allocation) ----------------
static __device__ __nv_bfloat16 g_A1h[(size_t)RR * CCH];   // 100 MB
static __device__ __nv_bfloat16 g_A1l[(size_t)RR * CCH];   // 100 MB
static __device__ __nv_bfloat16 g_A2h[(size_t)RR * MCH];   // 33 MB
static __device__ __nv_bfloat16 g_A2l[(size_t)RR * MCH];   // 33 MB
static __device__ __nv_bfloat16 g_W1h[MCH * CCH], g_W1l[MCH * CCH];
static __device__ __nv_bfloat16 g_W2h[MCH * MCH], g_W2l[MCH * MCH];
static __device__ float g_x1[(size_t)RR * MCH];            // 67 MB
static __device__ float g_x2[(size_t)RR * MCH];            // 67 MB
static __device__ int   g_kidx[RR * 3];
static __device__ float g_kw[RR * 3];
static __device__ float g_stats[4 * MCH];                  // sum1, sq1, sum2, sq2
static __device__ float g_affine[4 * MCH];                 // scale1, shift1, scale2, shift2

// ---------------- helpers ----------------
__device__ __forceinline__ uint32_t smem_u32(const void* p) {
    uint32_t a;
    asm("{ .reg .u64 t; cvta.to.shared.u64 t, %1; cvt.u32.u64 %0, t; }" : "=r"(a) : "l"(p));
    return a;
}
__device__ __forceinline__ void cp16(uint32_t saddr, const void* g) {
    asm volatile("cp.async.cg.shared.global [%0], [%1], 16;" :: "r"(saddr), "l"(g) : "memory");
}

#define MMA16816(c, a, b) \
    asm volatile("mma.sync.aligned.m16n8k16.row.col.f32.bf16.bf16.f32 " \
                 "{%0,%1,%2,%3},{%4,%5,%6,%7},{%8,%9},{%0,%1,%2,%3};" \
                 : "+f"((c)[0]), "+f"((c)[1]), "+f"((c)[2]), "+f"((c)[3]) \
                 : "r"((a)[0]), "r"((a)[1]), "r"((a)[2]), "r"((a)[3]), \
                   "r"((b)[0]), "r"((b)[1]))

// ---------------- zero stats ----------------
__global__ void zero_stats_kernel() {
    int i = blockIdx.x * blockDim.x + threadIdx.x;
    if (i < 4 * MCH) g_stats[i] = 0.0f;
}

// ---------------- KNN (top-3 smallest squared distances) ----------------
__global__ void knn_kernel(const float* __restrict__ xyz,
                           const float* __restrict__ centers) {
    __shared__ float sc[SS * 3];
    __shared__ float scn[SS];
    int p = blockIdx.x * blockDim.x + threadIdx.x;
    int b = p >> 13;
    for (int i = threadIdx.x; i < SS * 3; i += blockDim.x)
        sc[i] = centers[b * SS * 3 + i];
    __syncthreads();
    for (int s = threadIdx.x; s < SS; s += blockDim.x) {
        float c0 = sc[s*3], c1 = sc[s*3+1], c2 = sc[s*3+2];
        scn[s] = c0*c0 + c1*c1 + c2*c2;
    }
    __syncthreads();

    float x0 = xyz[p*3+0], x1 = xyz[p*3+1], x2 = xyz[p*3+2];
    float xx = x0*x0 + x1*x1 + x2*x2;

    float bd0 = 3.4e38f, bd1 = 3.4e38f, bd2 = 3.4e38f;
    int   bi0 = 0, bi1 = 0, bi2 = 0;
    for (int s = 0; s < SS; s++) {
        float c0 = sc[s*3], c1 = sc[s*3+1], c2 = sc[s*3+2];
        float dot = x0*c0 + x1*c1 + x2*c2;
        float d = xx - 2.0f * dot + scn[s];
        if (d < bd2) {
            if (d < bd1) {
                bd2 = bd1; bi2 = bi1;
                if (d < bd0) { bd1 = bd0; bi1 = bi0; bd0 = d; bi0 = s; }
                else         { bd1 = d;  bi1 = s; }
            } else { bd2 = d; bi2 = s; }
        }
    }
    float r0 = 1.0f / (bd0 + 1e-8f);
    float r1 = 1.0f / (bd1 + 1e-8f);
    float r2 = 1.0f / (bd2 + 1e-8f);
    float inv = 1.0f / (r0 + r1 + r2);
    g_kidx[p*3+0] = bi0; g_kidx[p*3+1] = bi1; g_kidx[p*3+2] = bi2;
    g_kw[p*3+0] = r0 * inv; g_kw[p*3+1] = r1 * inv; g_kw[p*3+2] = r2 * inv;
}

// ---------------- split helper ----------------
__device__ __forceinline__ void split_bf16(float v, __nv_bfloat16& h, __nv_bfloat16& l) {
    h = __float2bfloat16(v);
    l = __float2bfloat16(v - __bfloat162float(h));
}

// ---------------- interpolation + split to bf16 hi/lo ----------------
__global__ void interp_split_kernel(const float* __restrict__ H4,
                                    const float* __restrict__ H8,
                                    const float* __restrict__ H12) {
    int p = blockIdx.x;
    int b = p >> 13;
    __shared__ int   si[3];
    __shared__ float sw_[3];
    if (threadIdx.x < 3) {
        si[threadIdx.x]  = g_kidx[p*3 + threadIdx.x];
        sw_[threadIdx.x] = g_kw[p*3 + threadIdx.x];
    }
    __syncthreads();
    int c4  = threadIdx.x;        // 0..383
    int sec = c4 >> 7;
    int off = c4 & 127;
    const float* src = (sec == 0) ? H4 : ((sec == 1) ? H8 : H12);
    const float4* base = (const float4*)src + (size_t)b * SS * 128;

    float4 a = make_float4(0.f, 0.f, 0.f, 0.f);
#pragma unroll
    for (int k = 0; k < 3; k++) {
        float4 v = base[si[k] * 128 + off];
        float w = sw_[k];
        a.x += w * v.x; a.y += w * v.y; a.z += w * v.z; a.w += w * v.w;
    }
    __nv_bfloat16 h[4], l[4];
    split_bf16(a.x, h[0], l[0]); split_bf16(a.y, h[1], l[1]);
    split_bf16(a.z, h[2], l[2]); split_bf16(a.w, h[3], l[3]);
    size_t idx = (size_t)p * CCH + c4 * 4;
    *(uint2*)(g_A1h + idx) = *(uint2*)h;
    *(uint2*)(g_A1l + idx) = *(uint2*)l;
}

// ---------------- weight split ----------------
template<int WHICH>
__global__ void wsplit_kernel(const float* __restrict__ W) {
    const int n = WHICH ? (MCH * MCH) : (MCH * CCH);
    __nv_bfloat16* H = WHICH ? g_W2h : g_W1h;
    __nv_bfloat16* L = WHICH ? g_W2l : g_W1l;
    int i = blockIdx.x * blockDim.x + threadIdx.x;
    if (i < n) {
        __nv_bfloat16 h, l;
        split_bf16(W[i], h, l);
        H[i] = h; L[i] = l;
    }
}

// ---------------- bf16 split-precision HMMA GEMM ----------------
// CTA tile 128(M)x128(N), K-chunk 32, cp.async double buffer.
// 8 warps: 2(M) x 4(N); warp tile 64x32; mma m16n8k16.
// out[row,col] = sum_k A[row,k]*W[col,k] + bias[col]
// where A*W = Ah*Wh + Ah*Wl + Al*Wh (fp32 accum).
//
// SMEM stage layout (padded rows: 32 bf16 = 64B data, stride 80B):
//   Ah @ 0, Al @ 10240, Wh @ 20480, Wl @ 30720; stage stride 40960.
#define STG_BYTES 40960
#define ROWSTRIDE 80

template<int KTOT, int LAYER>
__global__ void __launch_bounds__(256, 1)
hmma_gemm_kernel(const float* __restrict__ bias) {
    extern __shared__ __align__(128) char smem[];
    const __nv_bfloat16* Ah = LAYER ? g_A2h : g_A1h;
    const __nv_bfloat16* Al = LAYER ? g_A2l : g_A1l;
    const __nv_bfloat16* Wh = LAYER ? g_W2h : g_W1h;
    const __nv_bfloat16* Wl = LAYER ? g_W2l : g_W1l;
    float* out = LAYER ? g_x2 : g_x1;

    const int tid  = threadIdx.x;
    const int wid  = tid >> 5;
    const int lane = tid & 31;
    const int wm   = wid >> 2;        // 0..1
    const int wn   = wid & 3;         // 0..3
    const int brow = blockIdx.y * 128;
    const int bcol = blockIdx.x * 128;

    const uint32_t sbase = smem_u32(smem);

    // loader: each thread brings 2 x 16B per tensor per stage
    const int lrow0 = tid >> 2;            // rows covered: lin = tid + j*256
    const int lseg0 = tid & 3;

    float acc[4][4][4];
#pragma unroll
    for (int mf = 0; mf < 4; mf++)
#pragma unroll
        for (int nf = 0; nf < 4; nf++)
#pragma unroll
            for (int q = 0; q < 4; q++) acc[mf][nf][q] = 0.f;

    constexpr int NCH = KTOT / 32;

    auto issue = [&](int chunk, int stage) {
        const uint32_t sb = sbase + stage * STG_BYTES;
        const int kc = chunk * 32;
#pragma unroll
        for (int j = 0; j < 2; j++) {
            int lin = tid + j * 256;       // 0..511
            int row = lin >> 2;
            int seg = lin & 3;
            uint32_t so = row * ROWSTRIDE + seg * 16;
            size_t goA = (size_t)(brow + row) * KTOT + kc + seg * 8;
            size_t goW = (size_t)(bcol + row) * KTOT + kc + seg * 8;
            cp16(sb + so,         Ah + goA);
            cp16(sb + 10240 + so, Al + goA);
            cp16(sb + 20480 + so, Wh + goW);
            cp16(sb + 30720 + so, Wl + goW);
        }
        asm volatile("cp.async.commit_group;" ::: "memory");
    };

    issue(0, 0);

    const int aRow0 = wm * 64 + (lane >> 2);
    const int bRow0 = wn * 32 + (lane >> 2);
    const int colB  = (lane & 3) * 4;      // byte offset of k-pair within row

    for (int c = 0; c < NCH; c++) {
        if (c + 1 < NCH) {
            issue(c + 1, (c + 1) & 1);
            asm volatile("cp.async.wait_group 1;" ::: "memory");
        } else {
            asm volatile("cp.async.wait_group 0;" ::: "memory");
        }
        __syncthreads();

        const char* st = smem + (c & 1) * STG_BYTES;
        const char* sAh = st;
        const char* sAl = st + 10240;
        const char* sWh = st + 20480;
        const char* sWl = st + 30720;

#pragma unroll
        for (int kk = 0; kk < 2; kk++) {
            const int kb = kk * 32 + colB;
            uint32_t ah[4][4], alr[4][4], bb[4][2];
#pragma unroll
            for (int mf = 0; mf < 4; mf++) {
                const char* ba = sAh + (aRow0 + mf * 16) * ROWSTRIDE + kb;
                ah[mf][0] = *(const uint32_t*)(ba);
                ah[mf][1] = *(const uint32_t*)(ba + 8 * ROWSTRIDE);
                ah[mf][2] = *(const uint32_t*)(ba + 16);
                ah[mf][3] = *(const uint32_t*)(ba + 8 * ROWSTRIDE + 16);
                const char* bl = sAl + (aRow0 + mf * 16) * ROWSTRIDE + kb;
                alr[mf][0] = *(const uint32_t*)(bl);
                alr[mf][1] = *(const uint32_t*)(bl + 8 * ROWSTRIDE);
                alr[mf][2] = *(const uint32_t*)(bl + 16);
                alr[mf][3] = *(const uint32_t*)(bl + 8 * ROWSTRIDE + 16);
            }
#pragma unroll
            for (int nf = 0; nf < 4; nf++) {
                const char* bw = sWh + (bRow0 + nf * 8) * ROWSTRIDE + kb;
                bb[nf][0] = *(const uint32_t*)(bw);
                bb[nf][1] = *(const uint32_t*)(bw + 16);
            }
            // Ah*Wh and Al*Wh
#pragma unroll
            for (int mf = 0; mf < 4; mf++)
#pragma unroll
                for (int nf = 0; nf < 4; nf++) {
                    MMA16816(acc[mf][nf], ah[mf], bb[nf]);
                    MMA16816(acc[mf][nf], alr[mf], bb[nf]);
                }
            // Wl pass: Ah*Wl
#pragma unroll
            for (int nf = 0; nf < 4; nf++) {
                const char* bw = sWl + (bRow0 + nf * 8) * ROWSTRIDE + kb;
                bb[nf][0] = *(const uint32_t*)(bw);
                bb[nf][1] = *(const uint32_t*)(bw + 16);
            }
#pragma unroll
            for (int mf = 0; mf < 4; mf++)
#pragma unroll
                for (int nf = 0; nf < 4; nf++)
                    MMA16816(acc[mf][nf], ah[mf], bb[nf]);
        }
        __syncthreads();
    }

    // epilogue
    const int r0 = brow + wm * 64 + (lane >> 2);
    const int cc = bcol + wn * 32 + (lane & 3) * 2;
#pragma unroll
    for (int nf = 0; nf < 4; nf++) {
        int col = cc + nf * 8;
        float b0 = bias[col], b1 = bias[col + 1];
#pragma unroll
        for (int mf = 0; mf < 4; mf++) {
#pragma unroll
            for (int rr = 0; rr < 2; rr++) {
                int row = r0 + mf * 16 + rr * 8;
                float2 v = make_float2(acc[mf][nf][rr * 2 + 0] + b0,
                                       acc[mf][nf][rr * 2 + 1] + b1);
                *(float2*)&out[(size_t)row * MCH + col] = v;
            }
        }
    }
}

// ---------------- per-channel sum / sumsq over 32768 rows ----------------
__global__ void colstats_kernel(int layer) {
    const float* x = layer ? g_x2 : g_x1;
    float* sum = &g_stats[layer * 2 * MCH];
    float* sq  = sum + MCH;
    int c0 = threadIdx.x;                 // 0..255
    int rbase = blockIdx.x * 128;
    float s0 = 0.f, q0 = 0.f, s1 = 0.f, q1 = 0.f;
    for (int r = 0; r < 128; r++) {
        const float* row = x + (size_t)(rbase + r) * MCH;
        float v0 = row[c0];
        float v1 = row[c0 + 256];
        s0 += v0; q0 += v0 * v0;
        s1 += v1; q1 += v1 * v1;
    }
    atomicAdd(&sum[c0], s0);       atomicAdd(&sq[c0], q0);
    atomicAdd(&sum[c0 + 256], s1); atomicAdd(&sq[c0 + 256], q1);
}

// ---------------- BN finalize ----------------
__global__ void finalize_kernel(const float* __restrict__ gamma,
                                const float* __restrict__ beta, int layer) {
    int c = threadIdx.x;   // 512 threads
    float mean = g_stats[layer * 2 * MCH + c] * (1.0f / RR);
    float var  = g_stats[layer * 2 * MCH + MCH + c] * (1.0f / RR) - mean * mean;
    float rstd = rsqrtf(var + 1e-5f);
    float sc = gamma[c] * rstd;
    g_affine[layer * 2 * MCH + c]       = sc;
    g_affine[layer * 2 * MCH + MCH + c] = beta[c] - mean * sc;
}

// ---------------- layer2 input map: relu(bn1(x1)) -> split bf16 ----------------
__global__ void map2_kernel() {
    int i = blockIdx.x * blockDim.x + threadIdx.x;   // float4 index over RR*128
    int c4 = i & 127;
    float4 v = ((const float4*)g_x1)[i];
    float4 s = ((const float4*)g_affine)[c4];
    float4 t = ((const float4*)(g_affine + MCH))[c4];
    v.x = fmaxf(fmaf(v.x, s.x, t.x), 0.f);
    v.y = fmaxf(fmaf(v.y, s.y, t.y), 0.f);
    v.z = fmaxf(fmaf(v.z, s.z, t.z), 0.f);
    v.w = fmaxf(fmaf(v.w, s.w, t.w), 0.f);
    __nv_bfloat16 h[4], l[4];
    split_bf16(v.x, h[0], l[0]); split_bf16(v.y, h[1], l[1]);
    split_bf16(v.z, h[2], l[2]); split_bf16(v.w, h[3], l[3]);
    size_t idx = (size_t)i * 4;
    *(uint2*)(g_A2h + idx) = *(uint2*)h;
    *(uint2*)(g_A2l + idx) = *(uint2*)l;
}

// ---------------- final map: out = relu(x2 * scale2 + shift2) ----------------
__global__ void finalmap_kernel(float* __restrict__ out) {
    int i = blockIdx.x * blockDim.x + threadIdx.x;
    int c4 = i & 127;
    float4 v  = ((const float4*)g_x2)[i];
    float4 s  = ((const float4*)(g_affine + 2 * MCH))[c4];
    float4 t  = ((const float4*)(g_affine + 3 * MCH))[c4];
    v.x = fmaxf(fmaf(v.x, s.x, t.x), 0.f);
    v.y = fmaxf(fmaf(v.y, s.y, t.y), 0.f);
    v.z = fmaxf(fmaf(v.z, s.z, t.z), 0.f);
    v.w = fmaxf(fmaf(v.w, s.w, t.w), 0.f);
    ((float4*)out)[i] = v;
}

// ---------------- launch ----------------
extern "C" void kernel_launch(void* const* d_in, const int* in_sizes, int n_in,
                              void* d_out, int out_size) {
    const float* xyz     = (const float*)d_in[0];
    const float* centers = (const float*)d_in[1];
    const float* H4      = (const float*)d_in[2];
    const float* H8      = (const float*)d_in[3];
    const float* H12     = (const float*)d_in[4];
    const float* W1      = (const float*)d_in[5];
    const float* b1      = (const float*)d_in[6];
    const float* g1      = (const float*)d_in[7];
    const float* beta1   = (const float*)d_in[8];
    const float* W2      = (const float*)d_in[9];
    const float* b2      = (const float*)d_in[10];
    const float* g2      = (const float*)d_in[11];
    const float* beta2   = (const float*)d_in[12];
    float* out = (float*)d_out;

    const int SMEM_BYTES = 2 * STG_BYTES;   // 81920
    cudaFuncSetAttribute(hmma_gemm_kernel<CCH, 0>,
                         cudaFuncAttributeMaxDynamicSharedMemorySize, SMEM_BYTES);
    cudaFuncSetAttribute(hmma_gemm_kernel<MCH, 1>,
                         cudaFuncAttributeMaxDynamicSharedMemorySize, SMEM_BYTES);

    zero_stats_kernel<<<2, 1024>>>();
    knn_kernel<<<RR / 256, 256>>>(xyz, centers);
    wsplit_kernel<0><<<(MCH * CCH) / 256, 256>>>(W1);
    wsplit_kernel<1><<<(MCH * MCH) / 256, 256>>>(W2);
    interp_split_kernel<<<RR, 384>>>(H4, H8, H12);

    dim3 gg(MCH / 128, RR / 128);   // (4, 256): n-blocks fastest for A-tile L2 reuse
    hmma_gemm_kernel<CCH, 0><<<gg, 256, SMEM_BYTES>>>(b1);

    colstats_kernel<<<RR / 128, 256>>>(0);
    finalize_kernel<<<1, 512>>>(g1, beta1, 0);
    map2_kernel<<<(RR * 128) / 256, 256>>>();

    hmma_gemm_kernel<MCH, 1><<<gg, 256, SMEM_BYTES>>>(b2);

    colstats_kernel<<<RR / 128, 256>>>(1);
    finalize_kernel<<<1, 512>>>(g2, beta2, 1);

    finalmap_kernel<<<(RR * 128) / 256, 256>>>(out);
}

// round 6
// speedup vs baseline: 3.3039x; 1.6046x over previous
#include <cuda_runtime.h>
#include <cuda_fp16.h>
#include <cstdint>
#include <math.h>

#define BB 4
#define NN 8192
#define SS 512
#define CCH 1536
#define MCH 512
#define RR (BB*NN)   // 32768 rows

// ---------------- scratch (static device globals; no allocation) ----------------
static __device__ __half g_A1[(size_t)RR * CCH];           // 100 MB (fp16 interp)
static __device__ __half g_A2[(size_t)RR * MCH];           // 33 MB
static __device__ __half g_W1h[MCH * CCH], g_W1l[MCH * CCH];
static __device__ __half g_W2h[MCH * MCH], g_W2l[MCH * MCH];
static __device__ float g_x1[(size_t)RR * MCH];            // 67 MB
static __device__ float g_x2[(size_t)RR * MCH];            // 67 MB
static __device__ int   g_kidx[RR * 3];
static __device__ float g_kw[RR * 3];
static __device__ float g_stats[4 * MCH];                  // sum1, sq1, sum2, sq2
static __device__ float g_affine[4 * MCH];                 // scale1, shift1, scale2, shift2

// ---------------- helpers ----------------
__device__ __forceinline__ uint32_t smem_u32(const void* p) {
    uint32_t a;
    asm("{ .reg .u64 t; cvta.to.shared.u64 t, %1; cvt.u32.u64 %0, t; }" : "=r"(a) : "l"(p));
    return a;
}
__device__ __forceinline__ void cp16(uint32_t saddr, const void* g) {
    asm volatile("cp.async.cg.shared.global [%0], [%1], 16;" :: "r"(saddr), "l"(g) : "memory");
}

#define LDSM4(R0, R1, R2, R3, ADDR) \
    asm volatile("ldmatrix.sync.aligned.m8n8.x4.shared.b16 {%0,%1,%2,%3}, [%4];" \
                 : "=r"(R0), "=r"(R1), "=r"(R2), "=r"(R3) : "r"(ADDR))

#define MMA16816(c, a, b) \
    asm volatile("mma.sync.aligned.m16n8k16.row.col.f32.f16.f16.f32 " \
                 "{%0,%1,%2,%3},{%4,%5,%6,%7},{%8,%9},{%0,%1,%2,%3};" \
                 : "+f"((c)[0]), "+f"((c)[1]), "+f"((c)[2]), "+f"((c)[3]) \
                 : "r"((a)[0]), "r"((a)[1]), "r"((a)[2]), "r"((a)[3]), \
                   "r"((b)[0]), "r"((b)[1]))

// ---------------- zero stats ----------------
__global__ void zero_stats_kernel() {
    int i = blockIdx.x * blockDim.x + threadIdx.x;
    if (i < 4 * MCH) g_stats[i] = 0.0f;
}

// ---------------- KNN (top-3 smallest squared distances) ----------------
__global__ void knn_kernel(const float* __restrict__ xyz,
                           const float* __restrict__ centers) {
    __shared__ float sc[SS * 3];
    __shared__ float scn[SS];
    int p = blockIdx.x * blockDim.x + threadIdx.x;
    int b = p >> 13;
    for (int i = threadIdx.x; i < SS * 3; i += blockDim.x)
        sc[i] = centers[b * SS * 3 + i];
    __syncthreads();
    for (int s = threadIdx.x; s < SS; s += blockDim.x) {
        float c0 = sc[s*3], c1 = sc[s*3+1], c2 = sc[s*3+2];
        scn[s] = c0*c0 + c1*c1 + c2*c2;
    }
    __syncthreads();

    float x0 = xyz[p*3+0], x1 = xyz[p*3+1], x2 = xyz[p*3+2];
    float xx = x0*x0 + x1*x1 + x2*x2;

    float bd0 = 3.4e38f, bd1 = 3.4e38f, bd2 = 3.4e38f;
    int   bi0 = 0, bi1 = 0, bi2 = 0;
    for (int s = 0; s < SS; s++) {
        float c0 = sc[s*3], c1 = sc[s*3+1], c2 = sc[s*3+2];
        float dot = x0*c0 + x1*c1 + x2*c2;
        float d = xx - 2.0f * dot + scn[s];
        if (d < bd2) {
            if (d < bd1) {
                bd2 = bd1; bi2 = bi1;
                if (d < bd0) { bd1 = bd0; bi1 = bi0; bd0 = d; bi0 = s; }
                else         { bd1 = d;  bi1 = s; }
            } else { bd2 = d; bi2 = s; }
        }
    }
    float r0 = 1.0f / (bd0 + 1e-8f);
    float r1 = 1.0f / (bd1 + 1e-8f);
    float r2 = 1.0f / (bd2 + 1e-8f);
    float inv = 1.0f / (r0 + r1 + r2);
    g_kidx[p*3+0] = bi0; g_kidx[p*3+1] = bi1; g_kidx[p*3+2] = bi2;
    g_kw[p*3+0] = r0 * inv; g_kw[p*3+1] = r1 * inv; g_kw[p*3+2] = r2 * inv;
}

// ---------------- split helper (fp16 hi/lo) ----------------
__device__ __forceinline__ void split_h(float v, __half& h, __half& l) {
    h = __float2half(v);
    l = __float2half(v - __half2float(h));
}

// ---------------- interpolation -> fp16 A1 ----------------
__global__ void interp_kernel(const float* __restrict__ H4,
                              const float* __restrict__ H8,
                              const float* __restrict__ H12) {
    int p = blockIdx.x;
    int b = p >> 13;
    __shared__ int   si[3];
    __shared__ float sw_[3];
    if (threadIdx.x < 3) {
        si[threadIdx.x]  = g_kidx[p*3 + threadIdx.x];
        sw_[threadIdx.x] = g_kw[p*3 + threadIdx.x];
    }
    __syncthreads();
    int c4  = threadIdx.x;        // 0..383
    int sec = c4 >> 7;
    int off = c4 & 127;
    const float* src = (sec == 0) ? H4 : ((sec == 1) ? H8 : H12);
    const float4* base = (const float4*)src + (size_t)b * SS * 128;

    float4 a = make_float4(0.f, 0.f, 0.f, 0.f);
#pragma unroll
    for (int k = 0; k < 3; k++) {
        float4 v = base[si[k] * 128 + off];
        float w = sw_[k];
        a.x += w * v.x; a.y += w * v.y; a.z += w * v.z; a.w += w * v.w;
    }
    __half h[4];
    h[0] = __float2half(a.x); h[1] = __float2half(a.y);
    h[2] = __float2half(a.z); h[3] = __float2half(a.w);
    *(uint2*)(g_A1 + (size_t)p * CCH + c4 * 4) = *(uint2*)h;
}

// ---------------- weight split (fp16 hi/lo) ----------------
template<int WHICH>
__global__ void wsplit_kernel(const float* __restrict__ W) {
    const int n = WHICH ? (MCH * MCH) : (MCH * CCH);
    __half* H = WHICH ? g_W2h : g_W1h;
    __half* L = WHICH ? g_W2l : g_W1l;
    int i = blockIdx.x * blockDim.x + threadIdx.x;
    if (i < n) {
        __half h, l;
        split_h(W[i], h, l);
        H[i] = h; L[i] = l;
    }
}

// ---------------- fp16 W-split HMMA GEMM with fused column stats ----------------
// CTA tile 128(M)x128(N), K-chunk 32, cp.async double buffer, ldmatrix frags.
// 8 warps: 2(M) x 4(N); warp tile 64x32; mma m16n8k16.
// out[row,col] = sum_k A[row,k]*(Wh+Wl)[col,k] + bias[col]   (fp32 accum)
// SMEM stage: A @0, Wh @10240, Wl @20480; padded rows (64B data, 80B stride).
#define STG_BYTES 30720
#define ROWSTRIDE 80

template<int KTOT, int LAYER>
__global__ void __launch_bounds__(256, 2)
hmma_gemm_kernel(const float* __restrict__ bias) {
    extern __shared__ __align__(128) char smem[];
    const __half* A  = LAYER ? g_A2  : g_A1;
    const __half* Wh = LAYER ? g_W2h : g_W1h;
    const __half* Wl = LAYER ? g_W2l : g_W1l;
    float* out = LAYER ? g_x2 : g_x1;
    float* statSum = g_stats + LAYER * 2 * MCH;
    float* statSq  = statSum + MCH;

    const int tid  = threadIdx.x;
    const int wid  = tid >> 5;
    const int lane = tid & 31;
    const int wm   = wid >> 2;        // 0..1
    const int wn   = wid & 3;         // 0..3
    const int brow = blockIdx.y * 128;
    const int bcol = blockIdx.x * 128;

    const uint32_t sbase = smem_u32(smem);

    // ldmatrix per-lane address components
    const int arow  = (lane & 7) + ((lane >> 3) & 1) * 8;   // A: phases 0/1 rows, 2/3 k+8
    const int akoff = (lane >> 4) * 16;
    const int brw   = (lane & 7) + ((lane >> 4) & 1) * 8;   // B: phases 0/1 k, 2/3 rows+8
    const int bkoff = ((lane >> 3) & 1) * 16;

    const uint32_t aBase  = sbase + (wm * 64 + arow) * ROWSTRIDE + akoff;
    const uint32_t bhBase = sbase + 10240 + (wn * 32 + brw) * ROWSTRIDE + bkoff;
    const uint32_t blBase = bhBase + 10240;

    float acc[4][4][4];
#pragma unroll
    for (int mf = 0; mf < 4; mf++)
#pragma unroll
        for (int nf = 0; nf < 4; nf++)
#pragma unroll
            for (int q = 0; q < 4; q++) acc[mf][nf][q] = 0.f;

    constexpr int NCH = KTOT / 32;

    auto issue = [&](int chunk, int stage) {
        const uint32_t sb = sbase + stage * STG_BYTES;
        const int kc = chunk * 32;
#pragma unroll
        for (int j = 0; j < 2; j++) {
            int lin = tid + j * 256;       // 0..511
            int row = lin >> 2;
            int seg = lin & 3;
            uint32_t so = row * ROWSTRIDE + seg * 16;
            size_t goA = (size_t)(brow + row) * KTOT + kc + seg * 8;
            size_t goW = (size_t)(bcol + row) * KTOT + kc + seg * 8;
            cp16(sb + so,         A  + goA);
            cp16(sb + 10240 + so, Wh + goW);
            cp16(sb + 20480 + so, Wl + goW);
        }
        asm volatile("cp.async.commit_group;" ::: "memory");
    };

    issue(0, 0);

    for (int c = 0; c < NCH; c++) {
        if (c + 1 < NCH) {
            issue(c + 1, (c + 1) & 1);
            asm volatile("cp.async.wait_group 1;" ::: "memory");
        } else {
            asm volatile("cp.async.wait_group 0;" ::: "memory");
        }
        __syncthreads();

        const uint32_t stg = (c & 1) * STG_BYTES;

#pragma unroll
        for (int kk = 0; kk < 2; kk++) {
            const int kb = kk * 32;   // bytes into 64B row
            uint32_t a[4][4], bh[4][2], bl[4][2];
#pragma unroll
            for (int mf = 0; mf < 4; mf++)
                LDSM4(a[mf][0], a[mf][1], a[mf][2], a[mf][3],
                      aBase + stg + mf * (16 * ROWSTRIDE) + kb);
#pragma unroll
            for (int np = 0; np < 2; np++)
                LDSM4(bh[np*2][0], bh[np*2][1], bh[np*2+1][0], bh[np*2+1][1],
                      bhBase + stg + np * (16 * ROWSTRIDE) + kb);
#pragma unroll
            for (int np = 0; np < 2; np++)
                LDSM4(bl[np*2][0], bl[np*2][1], bl[np*2+1][0], bl[np*2+1][1],
                      blBase + stg + np * (16 * ROWSTRIDE) + kb);
#pragma unroll
            for (int mf = 0; mf < 4; mf++)
#pragma unroll
                for (int nf = 0; nf < 4; nf++) {
                    MMA16816(acc[mf][nf], a[mf], bh[nf]);
                    MMA16816(acc[mf][nf], a[mf], bl[nf]);
                }
        }
        __syncthreads();
    }

    // epilogue: write out + fused column stats
    const int r0 = brow + wm * 64 + (lane >> 2);
    const int cc = bcol + wn * 32 + (lane & 3) * 2;
    float s[8], q[8];
#pragma unroll
    for (int i = 0; i < 8; i++) { s[i] = 0.f; q[i] = 0.f; }

#pragma unroll
    for (int nf = 0; nf < 4; nf++) {
        int col = cc + nf * 8;
        float b0 = bias[col], b1 = bias[col + 1];
#pragma unroll
        for (int mf = 0; mf < 4; mf++) {
#pragma unroll
            for (int rr = 0; rr < 2; rr++) {
                int row = r0 + mf * 16 + rr * 8;
                float v0 = acc[mf][nf][rr * 2 + 0] + b0;
                float v1 = acc[mf][nf][rr * 2 + 1] + b1;
                *(float2*)&out[(size_t)row * MCH + col] = make_float2(v0, v1);
                s[nf*2]   += v0; q[nf*2]   += v0 * v0;
                s[nf*2+1] += v1; q[nf*2+1] += v1 * v1;
            }
        }
    }
    // reduce over lanes {l, l+4, ..., l+28} (same columns, different rows)
#pragma unroll
    for (int off = 16; off >= 4; off >>= 1) {
#pragma unroll
        for (int i = 0; i < 8; i++) {
            s[i] += __shfl_down_sync(0xffffffffu, s[i], off);
            q[i] += __shfl_down_sync(0xffffffffu, q[i], off);
        }
    }
    if ((lane >> 2) == 0) {
#pragma unroll
        for (int nf = 0; nf < 4; nf++) {
#pragma unroll
            for (int cbit = 0; cbit < 2; cbit++) {
                int col = cc + nf * 8 + cbit;
                atomicAdd(&statSum[col], s[nf*2 + cbit]);
                atomicAdd(&statSq[col],  q[nf*2 + cbit]);
            }
        }
    }
}

// ---------------- BN finalize ----------------
__global__ void finalize_kernel(const float* __restrict__ gamma,
                                const float* __restrict__ beta, int layer) {
    int c = threadIdx.x;   // 512 threads
    float mean = g_stats[layer * 2 * MCH + c] * (1.0f / RR);
    float var  = g_stats[layer * 2 * MCH + MCH + c] * (1.0f / RR) - mean * mean;
    float rstd = rsqrtf(var + 1e-5f);
    float sc = gamma[c] * rstd;
    g_affine[layer * 2 * MCH + c]       = sc;
    g_affine[layer * 2 * MCH + MCH + c] = beta[c] - mean * sc;
}

// ---------------- layer2 input map: relu(bn1(x1)) -> fp16 A2 ----------------
__global__ void map2_kernel() {
    int i = blockIdx.x * blockDim.x + threadIdx.x;   // float4 index over RR*128
    int c4 = i & 127;
    float4 v = ((const float4*)g_x1)[i];
    float4 s = ((const float4*)g_affine)[c4];
    float4 t = ((const float4*)(g_affine + MCH))[c4];
    v.x = fmaxf(fmaf(v.x, s.x, t.x), 0.f);
    v.y = fmaxf(fmaf(v.y, s.y, t.y), 0.f);
    v.z = fmaxf(fmaf(v.z, s.z, t.z), 0.f);
    v.w = fmaxf(fmaf(v.w, s.w, t.w), 0.f);
    __half h[4];
    h[0] = __float2half(v.x); h[1] = __float2half(v.y);
    h[2] = __float2half(v.z); h[3] = __float2half(v.w);
    *(uint2*)(g_A2 + (size_t)i * 4) = *(uint2*)h;
}

// ---------------- final map: out = relu(x2 * scale2 + shift2) ----------------
__global__ void finalmap_kernel(float* __restrict__ out) {
    int i = blockIdx.x * blockDim.x + threadIdx.x;
    int c4 = i & 127;
    float4 v  = ((const float4*)g_x2)[i];
    float4 s  = ((const float4*)(g_affine + 2 * MCH))[c4];
    float4 t  = ((const float4*)(g_affine + 3 * MCH))[c4];
    v.x = fmaxf(fmaf(v.x, s.x, t.x), 0.f);
    v.y = fmaxf(fmaf(v.y, s.y, t.y), 0.f);
    v.z = fmaxf(fmaf(v.z, s.z, t.z), 0.f);
    v.w = fmaxf(fmaf(v.w, s.w, t.w), 0.f);
    ((float4*)out)[i] = v;
}

// ---------------- launch ----------------
extern "C" void kernel_launch(void* const* d_in, const int* in_sizes, int n_in,
                              void* d_out, int out_size) {
    const float* xyz     = (const float*)d_in[0];
    const float* centers = (const float*)d_in[1];
    const float* H4      = (const float*)d_in[2];
    const float* H8      = (const float*)d_in[3];
    const float* H12     = (const float*)d_in[4];
    const float* W1      = (const float*)d_in[5];
    const float* b1      = (const float*)d_in[6];
    const float* g1      = (const float*)d_in[7];
    const float* beta1   = (const float*)d_in[8];
    const float* W2      = (const float*)d_in[9];
    const float* b2      = (const float*)d_in[10];
    const float* g2      = (const float*)d_in[11];
    const float* beta2   = (const float*)d_in[12];
    float* out = (float*)d_out;

    const int SMEM_BYTES = 2 * STG_BYTES;   // 61440
    cudaFuncSetAttribute(hmma_gemm_kernel<CCH, 0>,
                         cudaFuncAttributeMaxDynamicSharedMemorySize, SMEM_BYTES);
    cudaFuncSetAttribute(hmma_gemm_kernel<MCH, 1>,
                         cudaFuncAttributeMaxDynamicSharedMemorySize, SMEM_BYTES);

    zero_stats_kernel<<<2, 1024>>>();
    knn_kernel<<<RR / 256, 256>>>(xyz, centers);
    wsplit_kernel<0><<<(MCH * CCH) / 256, 256>>>(W1);
    wsplit_kernel<1><<<(MCH * MCH) / 256, 256>>>(W2);
    interp_kernel<<<RR, 384>>>(H4, H8, H12);

    dim3 gg(MCH / 128, RR / 128);   // (4, 256): n-blocks fastest for A-tile L2 reuse
    hmma_gemm_kernel<CCH, 0><<<gg, 256, SMEM_BYTES>>>(b1);

    finalize_kernel<<<1, 512>>>(g1, beta1, 0);
    map2_kernel<<<(RR * 128) / 256, 256>>>();

    hmma_gemm_kernel<MCH, 1><<<gg, 256, SMEM_BYTES>>>(b2);

    finalize_kernel<<<1, 512>>>(g2, beta2, 1);

    finalmap_kernel<<<(RR * 128) / 256, 256>>>(out);
}

// round 7
// speedup vs baseline: 4.7983x; 1.4523x over previous
#include <cuda_runtime.h>
#include <cuda_fp16.h>
#include <cstdint>
#include <math.h>

#define BB 4
#define NN 8192
#define SS 512
#define CCH 1536
#define MCH 512
#define RR (BB*NN)   // 32768 rows

// ---------------- scratch (static device globals; no allocation) ----------------
static __device__ __half g_A1[(size_t)RR * CCH];           // 100 MB (fp16 interp)
static __device__ __half g_A2[(size_t)RR * MCH];           // 33 MB
static __device__ __half g_W1[MCH * CCH];
static __device__ __half g_W2[MCH * MCH];
static __device__ __half g_x1[(size_t)RR * MCH];           // 33 MB (pre-BN, fp16)
static __device__ __half g_x2[(size_t)RR * MCH];           // 33 MB (pre-BN, fp16)
static __device__ int   g_kidx[RR * 3];
static __device__ float g_kw[RR * 3];
static __device__ float g_stats[4 * MCH];                  // sum1, sq1, sum2, sq2
static __device__ float g_affine[4 * MCH];                 // scale1, shift1, scale2, shift2

// ---------------- helpers ----------------
__device__ __forceinline__ uint32_t smem_u32(const void* p) {
    uint32_t a;
    asm("{ .reg .u64 t; cvta.to.shared.u64 t, %1; cvt.u32.u64 %0, t; }" : "=r"(a) : "l"(p));
    return a;
}
__device__ __forceinline__ void cp16(uint32_t saddr, const void* g) {
    asm volatile("cp.async.cg.shared.global [%0], [%1], 16;" :: "r"(saddr), "l"(g) : "memory");
}

#define LDSM4(R0, R1, R2, R3, ADDR) \
    asm volatile("ldmatrix.sync.aligned.m8n8.x4.shared.b16 {%0,%1,%2,%3}, [%4];" \
                 : "=r"(R0), "=r"(R1), "=r"(R2), "=r"(R3) : "r"(ADDR))

#define MMA16816(c, a, b) \
    asm volatile("mma.sync.aligned.m16n8k16.row.col.f32.f16.f16.f32 " \
                 "{%0,%1,%2,%3},{%4,%5,%6,%7},{%8,%9},{%0,%1,%2,%3};" \
                 : "+f"((c)[0]), "+f"((c)[1]), "+f"((c)[2]), "+f"((c)[3]) \
                 : "r"((a)[0]), "r"((a)[1]), "r"((a)[2]), "r"((a)[3]), \
                   "r"((b)[0]), "r"((b)[1]))

// ---------------- zero stats ----------------
__global__ void zero_stats_kernel() {
    int i = blockIdx.x * blockDim.x + threadIdx.x;
    if (i < 4 * MCH) g_stats[i] = 0.0f;
}

// ---------------- KNN (top-3 smallest squared distances) ----------------
__global__ void knn_kernel(const float* __restrict__ xyz,
                           const float* __restrict__ centers) {
    __shared__ float sc[SS * 3];
    __shared__ float scn[SS];
    int p = blockIdx.x * blockDim.x + threadIdx.x;
    int b = p >> 13;
    for (int i = threadIdx.x; i < SS * 3; i += blockDim.x)
        sc[i] = centers[b * SS * 3 + i];
    __syncthreads();
    for (int s = threadIdx.x; s < SS; s += blockDim.x) {
        float c0 = sc[s*3], c1 = sc[s*3+1], c2 = sc[s*3+2];
        scn[s] = c0*c0 + c1*c1 + c2*c2;
    }
    __syncthreads();

    float x0 = xyz[p*3+0], x1 = xyz[p*3+1], x2 = xyz[p*3+2];
    float xx = x0*x0 + x1*x1 + x2*x2;

    float bd0 = 3.4e38f, bd1 = 3.4e38f, bd2 = 3.4e38f;
    int   bi0 = 0, bi1 = 0, bi2 = 0;
    for (int s = 0; s < SS; s++) {
        float c0 = sc[s*3], c1 = sc[s*3+1], c2 = sc[s*3+2];
        float dot = x0*c0 + x1*c1 + x2*c2;
        float d = xx - 2.0f * dot + scn[s];
        if (d < bd2) {
            if (d < bd1) {
                bd2 = bd1; bi2 = bi1;
                if (d < bd0) { bd1 = bd0; bi1 = bi0; bd0 = d; bi0 = s; }
                else         { bd1 = d;  bi1 = s; }
            } else { bd2 = d; bi2 = s; }
        }
    }
    float r0 = 1.0f / (bd0 + 1e-8f);
    float r1 = 1.0f / (bd1 + 1e-8f);
    float r2 = 1.0f / (bd2 + 1e-8f);
    float inv = 1.0f / (r0 + r1 + r2);
    g_kidx[p*3+0] = bi0; g_kidx[p*3+1] = bi1; g_kidx[p*3+2] = bi2;
    g_kw[p*3+0] = r0 * inv; g_kw[p*3+1] = r1 * inv; g_kw[p*3+2] = r2 * inv;
}

// ---------------- interpolation -> fp16 A1 ----------------
__global__ void interp_kernel(const float* __restrict__ H4,
                              const float* __restrict__ H8,
                              const float* __restrict__ H12) {
    int p = blockIdx.x;
    int b = p >> 13;
    __shared__ int   si[3];
    __shared__ float sw_[3];
    if (threadIdx.x < 3) {
        si[threadIdx.x]  = g_kidx[p*3 + threadIdx.x];
        sw_[threadIdx.x] = g_kw[p*3 + threadIdx.x];
    }
    __syncthreads();
    int c4  = threadIdx.x;        // 0..383
    int sec = c4 >> 7;
    int off = c4 & 127;
    const float* src = (sec == 0) ? H4 : ((sec == 1) ? H8 : H12);
    const float4* base = (const float4*)src + (size_t)b * SS * 128;

    float4 a = make_float4(0.f, 0.f, 0.f, 0.f);
#pragma unroll
    for (int k = 0; k < 3; k++) {
        float4 v = base[si[k] * 128 + off];
        float w = sw_[k];
        a.x += w * v.x; a.y += w * v.y; a.z += w * v.z; a.w += w * v.w;
    }
    __half h[4];
    h[0] = __float2half(a.x); h[1] = __float2half(a.y);
    h[2] = __float2half(a.z); h[3] = __float2half(a.w);
    *(uint2*)(g_A1 + (size_t)p * CCH + c4 * 4) = *(uint2*)h;
}

// ---------------- weight convert to fp16 ----------------
template<int WHICH>
__global__ void wconv_kernel(const float* __restrict__ W) {
    const int n = WHICH ? (MCH * MCH) : (MCH * CCH);
    __half* H = WHICH ? g_W2 : g_W1;
    int i = blockIdx.x * blockDim.x + threadIdx.x;
    if (i < n) H[i] = __float2half(W[i]);
}

// ---------------- fp16 HMMA GEMM with fused column stats, fp16 output ----------------
// CTA tile 128(M)x128(N), K-chunk 32, cp.async double buffer, ldmatrix frags.
// 8 warps: 2(M) x 4(N); warp tile 64x32; mma m16n8k16, fp32 accum.
// out[row,col] = sum_k A[row,k]*W[col,k] + bias[col]  (stored fp16; stats fp32)
// SMEM stage: A @0, W @10240; padded rows (64B data, 80B stride).
#define STG_BYTES 20480
#define ROWSTRIDE 80

template<int KTOT, int LAYER>
__global__ void __launch_bounds__(256, 2)
hmma_gemm_kernel(const float* __restrict__ bias) {
    extern __shared__ __align__(128) char smem[];
    const __half* A = LAYER ? g_A2 : g_A1;
    const __half* W = LAYER ? g_W2 : g_W1;
    __half* out = LAYER ? g_x2 : g_x1;
    float* statSum = g_stats + LAYER * 2 * MCH;
    float* statSq  = statSum + MCH;

    const int tid  = threadIdx.x;
    const int wid  = tid >> 5;
    const int lane = tid & 31;
    const int wm   = wid >> 2;        // 0..1
    const int wn   = wid & 3;         // 0..3
    const int brow = blockIdx.y * 128;
    const int bcol = blockIdx.x * 128;

    const uint32_t sbase = smem_u32(smem);

    // ldmatrix per-lane address components
    const int arow  = (lane & 7) + ((lane >> 3) & 1) * 8;   // A frag rows / k halves
    const int akoff = (lane >> 4) * 16;
    const int brw   = (lane & 7) + ((lane >> 4) & 1) * 8;   // B frag rows / k halves
    const int bkoff = ((lane >> 3) & 1) * 16;

    const uint32_t aBase = sbase + (wm * 64 + arow) * ROWSTRIDE + akoff;
    const uint32_t bBase = sbase + 10240 + (wn * 32 + brw) * ROWSTRIDE + bkoff;

    float acc[4][4][4];
#pragma unroll
    for (int mf = 0; mf < 4; mf++)
#pragma unroll
        for (int nf = 0; nf < 4; nf++)
#pragma unroll
            for (int q = 0; q < 4; q++) acc[mf][nf][q] = 0.f;

    constexpr int NCH = KTOT / 32;

    auto issue = [&](int chunk, int stage) {
        const uint32_t sb = sbase + stage * STG_BYTES;
        const int kc = chunk * 32;
#pragma unroll
        for (int j = 0; j < 2; j++) {
            int lin = tid + j * 256;       // 0..511
            int row = lin >> 2;
            int seg = lin & 3;
            uint32_t so = row * ROWSTRIDE + seg * 16;
            size_t goA = (size_t)(brow + row) * KTOT + kc + seg * 8;
            size_t goW = (size_t)(bcol + row) * KTOT + kc + seg * 8;
            cp16(sb + so,         A + goA);
            cp16(sb + 10240 + so, W + goW);
        }
        asm volatile("cp.async.commit_group;" ::: "memory");
    };

    issue(0, 0);

    for (int c = 0; c < NCH; c++) {
        if (c + 1 < NCH) {
            issue(c + 1, (c + 1) & 1);
            asm volatile("cp.async.wait_group 1;" ::: "memory");
        } else {
            asm volatile("cp.async.wait_group 0;" ::: "memory");
        }
        __syncthreads();

        const uint32_t stg = (c & 1) * STG_BYTES;

#pragma unroll
        for (int kk = 0; kk < 2; kk++) {
            const int kb = kk * 32;   // bytes into 64B row
            uint32_t a[4][4], bb[4][2];
#pragma unroll
            for (int mf = 0; mf < 4; mf++)
                LDSM4(a[mf][0], a[mf][1], a[mf][2], a[mf][3],
                      aBase + stg + mf * (16 * ROWSTRIDE) + kb);
#pragma unroll
            for (int np = 0; np < 2; np++)
                LDSM4(bb[np*2][0], bb[np*2][1], bb[np*2+1][0], bb[np*2+1][1],
                      bBase + stg + np * (16 * ROWSTRIDE) + kb);
#pragma unroll
            for (int mf = 0; mf < 4; mf++)
#pragma unroll
                for (int nf = 0; nf < 4; nf++)
                    MMA16816(acc[mf][nf], a[mf], bb[nf]);
        }
        __syncthreads();
    }

    // epilogue: write fp16 out + fused fp32 column stats
    const int r0 = brow + wm * 64 + (lane >> 2);
    const int cc = bcol + wn * 32 + (lane & 3) * 2;
    float s[8], q[8];
#pragma unroll
    for (int i = 0; i < 8; i++) { s[i] = 0.f; q[i] = 0.f; }

#pragma unroll
    for (int nf = 0; nf < 4; nf++) {
        int col = cc + nf * 8;
        float b0 = bias[col], b1 = bias[col + 1];
#pragma unroll
        for (int mf = 0; mf < 4; mf++) {
#pragma unroll
            for (int rr = 0; rr < 2; rr++) {
                int row = r0 + mf * 16 + rr * 8;
                float v0 = acc[mf][nf][rr * 2 + 0] + b0;
                float v1 = acc[mf][nf][rr * 2 + 1] + b1;
                __half2 hv = __floats2half2_rn(v0, v1);
                *(__half2*)&out[(size_t)row * MCH + col] = hv;
                s[nf*2]   += v0; q[nf*2]   += v0 * v0;
                s[nf*2+1] += v1; q[nf*2+1] += v1 * v1;
            }
        }
    }
    // reduce over lanes {l, l+4, ..., l+28} (same columns, different rows)
#pragma unroll
    for (int off = 16; off >= 4; off >>= 1) {
#pragma unroll
        for (int i = 0; i < 8; i++) {
            s[i] += __shfl_down_sync(0xffffffffu, s[i], off);
            q[i] += __shfl_down_sync(0xffffffffu, q[i], off);
        }
    }
    if ((lane >> 2) == 0) {
#pragma unroll
        for (int nf = 0; nf < 4; nf++) {
#pragma unroll
            for (int cbit = 0; cbit < 2; cbit++) {
                int col = cc + nf * 8 + cbit;
                atomicAdd(&statSum[col], s[nf*2 + cbit]);
                atomicAdd(&statSq[col],  q[nf*2 + cbit]);
            }
        }
    }
}

// ---------------- BN finalize ----------------
__global__ void finalize_kernel(const float* __restrict__ gamma,
                                const float* __restrict__ beta, int layer) {
    int c = threadIdx.x;   // 512 threads
    float mean = g_stats[layer * 2 * MCH + c] * (1.0f / RR);
    float var  = g_stats[layer * 2 * MCH + MCH + c] * (1.0f / RR) - mean * mean;
    float rstd = rsqrtf(var + 1e-5f);
    float sc = gamma[c] * rstd;
    g_affine[layer * 2 * MCH + c]       = sc;
    g_affine[layer * 2 * MCH + MCH + c] = beta[c] - mean * sc;
}

// ---------------- layer2 input map: relu(bn1(x1)) -> fp16 A2 ----------------
__global__ void map2_kernel() {
    int i = blockIdx.x * blockDim.x + threadIdx.x;   // 4-col group index over RR*128
    int c4 = i & 127;
    uint2 raw = ((const uint2*)g_x1)[i];
    __half2 h01 = *(__half2*)&raw.x;
    __half2 h23 = *(__half2*)&raw.y;
    float4 s = ((const float4*)g_affine)[c4];
    float4 t = ((const float4*)(g_affine + MCH))[c4];
    float v0 = fmaxf(fmaf(__low2float(h01),  s.x, t.x), 0.f);
    float v1 = fmaxf(fmaf(__high2float(h01), s.y, t.y), 0.f);
    float v2 = fmaxf(fmaf(__low2float(h23),  s.z, t.z), 0.f);
    float v3 = fmaxf(fmaf(__high2float(h23), s.w, t.w), 0.f);
    uint2 o;
    *(__half2*)&o.x = __floats2half2_rn(v0, v1);
    *(__half2*)&o.y = __floats2half2_rn(v2, v3);
    ((uint2*)g_A2)[i] = o;
}

// ---------------- final map: out = relu(x2 * scale2 + shift2) ----------------
__global__ void finalmap_kernel(float* __restrict__ out) {
    int i = blockIdx.x * blockDim.x + threadIdx.x;
    int c4 = i & 127;
    uint2 raw = ((const uint2*)g_x2)[i];
    __half2 h01 = *(__half2*)&raw.x;
    __half2 h23 = *(__half2*)&raw.y;
    float4 s = ((const float4*)(g_affine + 2 * MCH))[c4];
    float4 t = ((const float4*)(g_affine + 3 * MCH))[c4];
    float4 v;
    v.x = fmaxf(fmaf(__low2float(h01),  s.x, t.x), 0.f);
    v.y = fmaxf(fmaf(__high2float(h01), s.y, t.y), 0.f);
    v.z = fmaxf(fmaf(__low2float(h23),  s.z, t.z), 0.f);
    v.w = fmaxf(fmaf(__high2float(h23), s.w, t.w), 0.f);
    ((float4*)out)[i] = v;
}

// ---------------- launch ----------------
extern "C" void kernel_launch(void* const* d_in, const int* in_sizes, int n_in,
                              void* d_out, int out_size) {
    const float* xyz     = (const float*)d_in[0];
    const float* centers = (const float*)d_in[1];
    const float* H4      = (const float*)d_in[2];
    const float* H8      = (const float*)d_in[3];
    const float* H12     = (const float*)d_in[4];
    const float* W1      = (const float*)d_in[5];
    const float* b1      = (const float*)d_in[6];
    const float* g1      = (const float*)d_in[7];
    const float* beta1   = (const float*)d_in[8];
    const float* W2      = (const float*)d_in[9];
    const float* b2      = (const float*)d_in[10];
    const float* g2      = (const float*)d_in[11];
    const float* beta2   = (const float*)d_in[12];
    float* out = (float*)d_out;

    const int SMEM_BYTES = 2 * STG_BYTES;   // 40960
    cudaFuncSetAttribute(hmma_gemm_kernel<CCH, 0>,
                         cudaFuncAttributeMaxDynamicSharedMemorySize, SMEM_BYTES);
    cudaFuncSetAttribute(hmma_gemm_kernel<MCH, 1>,
                         cudaFuncAttributeMaxDynamicSharedMemorySize, SMEM_BYTES);

    zero_stats_kernel<<<2, 1024>>>();
    knn_kernel<<<RR / 256, 256>>>(xyz, centers);
    wconv_kernel<0><<<(MCH * CCH + 255) / 256, 256>>>(W1);
    wconv_kernel<1><<<(MCH * MCH + 255) / 256, 256>>>(W2);
    interp_kernel<<<RR, 384>>>(H4, H8, H12);

    dim3 gg(MCH / 128, RR / 128);   // (4, 256): n-blocks fastest for A-tile L2 reuse
    hmma_gemm_kernel<CCH, 0><<<gg, 256, SMEM_BYTES>>>(b1);

    finalize_kernel<<<1, 512>>>(g1, beta1, 0);
    map2_kernel<<<(RR * 128) / 256, 256>>>();

    hmma_gemm_kernel<MCH, 1><<<gg, 256, SMEM_BYTES>>>(b2);

    finalize_kernel<<<1, 512>>>(g2, beta2, 1);

    finalmap_kernel<<<(RR * 128) / 256, 256>>>(out);
}